// round 4
// baseline (speedup 1.0000x reference)
#include <cuda_runtime.h>
#include <math.h>

#define H 256
#define MAXE 500000
#define MAXG 256
#define FRONTIER_BONUS 0.5f
#define LN_EPS 1e-5f
#define F32_EPS 1.1920929e-07f
#define NBLK_P1 1184

// ---------------- device scratch ----------------
__device__ float g_w_att[H];          // att_vec @ W_edge
__device__ float g_qatt[MAXG];        // question_tokens[g] . (att_vec @ W_query)
__device__ float g_S[MAXG * H];       // segment sums of edge_tokens
__device__ int   g_maxenc[MAXG];      // orderable-int segment max of att_raw
__device__ int   g_cnt[MAXG];         // edges per graph
__device__ float g_att[MAXE];         // att_raw per edge

__device__ __forceinline__ int f2o(float f) {
    int i = __float_as_int(f);
    return i >= 0 ? i : (i ^ 0x7FFFFFFF);
}
__device__ __forceinline__ float o2f(int i) {
    return __int_as_float(i >= 0 ? i : (i ^ 0x7FFFFFFF));
}

// ---------------- fused setup: w_att + qatt + zeroing (one launch) --------
__global__ void __launch_bounds__(256) setup_k(
        const float* __restrict__ W_edge, const float* __restrict__ W_query,
        const float* __restrict__ att_vec, const float* __restrict__ qtok, int G) {
    int b = blockIdx.x, t = threadIdx.x;
    if (b == 0) {
        // w_att[t] = sum_i att_vec[i] * W_edge[i*H + t]  (coalesced per row)
        float s = 0.f;
        #pragma unroll 8
        for (int i = 0; i < H; i++)
            s = fmaf(__ldg(att_vec + i), __ldg(W_edge + i * H + t), s);
        g_w_att[t] = s;
    } else if (b <= 32) {
        // each of 32 blocks: compute w_q in shared, then qatt for 8 graphs
        __shared__ float wq[H];
        float s = 0.f;
        #pragma unroll 8
        for (int i = 0; i < H; i++)
            s = fmaf(__ldg(att_vec + i), __ldg(W_query + i * H + t), s);
        wq[t] = s;
        __syncthreads();
        int w = t >> 5, l = t & 31;
        int g = (b - 1) * 8 + w;
        if (g < G) {
            float s2 = 0.f;
            #pragma unroll
            for (int k = 0; k < 8; k++) {
                int j = l + 32 * k;
                s2 = fmaf(qtok[(size_t)g * H + j], wq[j], s2);
            }
            #pragma unroll
            for (int sh = 16; sh; sh >>= 1) s2 += __shfl_xor_sync(0xFFFFFFFFu, s2, sh);
            if (l == 0) g_qatt[g] = s2;
        }
    } else {
        // blocks 33..48: zero accumulators
        int idx = (b - 33) * 256 + t;
        for (int j = idx; j < G * H; j += 16 * 256) g_S[j] = 0.f;
        if (idx < G) { g_maxenc[idx] = f2o(-INFINITY); g_cnt[idx] = 0; }
    }
}

// ---------------- main streaming pass: half-warp per edge, x2 unroll -------
struct Run {
    float4 a0, a1, a2, a3;   // per-lane partial segment sum (16 floats)
    float rmax, qcur;
    int cur, rcnt;
};

__device__ __forceinline__ void addf4(float4& a, const float4& b) {
    a.x += b.x; a.y += b.y; a.z += b.z; a.w += b.w;
}

__device__ __forceinline__ void flush_run(Run& st, int hl) {
    if (st.cur < 0) return;
    float* Sp = g_S + st.cur * H;
    const float4 av[4] = {st.a0, st.a1, st.a2, st.a3};
    #pragma unroll
    for (int k = 0; k < 4; k++) {
        int base = (hl + 16 * k) * 4;
        atomicAdd(Sp + base + 0, av[k].x);
        atomicAdd(Sp + base + 1, av[k].y);
        atomicAdd(Sp + base + 2, av[k].z);
        atomicAdd(Sp + base + 3, av[k].w);
    }
    if (hl == 0) {
        atomicMax(&g_maxenc[st.cur], f2o(st.rmax));
        atomicAdd(&g_cnt[st.cur], st.rcnt);
    }
}

__device__ __forceinline__ void proc(Run& st, bool v, int g, int sv,
        const float4& x0, const float4& x1, const float4& x2, const float4& x3,
        const float4& w0, const float4& w1, const float4& w2, const float4& w3,
        int e, int hl) {
    if (g != st.cur) {
        flush_run(st, hl);
        st.a0 = st.a1 = st.a2 = st.a3 = make_float4(0.f, 0.f, 0.f, 0.f);
        st.rmax = -INFINITY; st.rcnt = 0; st.cur = g;
        st.qcur = g_qatt[g];
    }
    float d = x0.x * w0.x + x0.y * w0.y + x0.z * w0.z + x0.w * w0.w
            + x1.x * w1.x + x1.y * w1.y + x1.z * w1.z + x1.w * w1.w
            + x2.x * w2.x + x2.y * w2.y + x2.z * w2.z + x2.w * w2.w
            + x3.x * w3.x + x3.y * w3.y + x3.z * w3.z + x3.w * w3.w;
    // butterfly within 16-lane half (offsets <= 8 never cross halves)
    d += __shfl_xor_sync(0xFFFFFFFFu, d, 8);
    d += __shfl_xor_sync(0xFFFFFFFFu, d, 4);
    d += __shfl_xor_sync(0xFFFFFFFFu, d, 2);
    d += __shfl_xor_sync(0xFFFFFFFFu, d, 1);
    if (v) {
        addf4(st.a0, x0); addf4(st.a1, x1); addf4(st.a2, x2); addf4(st.a3, x3);
        float r = d + st.qcur;
        r = r > 0.f ? r : 0.2f * r;                   // LeakyReLU(0.2)
        if (sv == 0) r += FRONTIER_BONUS;             // candidate == frontier
        if (hl == 0) g_att[e] = r;
        st.rmax = fmaxf(st.rmax, r);
        st.rcnt++;
    }
}

__global__ void __launch_bounds__(256) pass1_k(const float* __restrict__ x,
        const int* __restrict__ batch, const int* __restrict__ sel, int E) {
    int chunk = (E + NBLK_P1 - 1) / NBLK_P1;
    int lo = blockIdx.x * chunk;
    int hi = min(E, lo + chunk);
    int w = threadIdx.x >> 5, l = threadIdx.x & 31;
    int half = l >> 4, hl = l & 15;

    // lane hl covers float4 indices {hl, hl+16, hl+32, hl+48} of its edge:
    // every LDG.128 is 16 consecutive float4s per half -> perfect 256B segments
    const float4* wav = (const float4*)g_w_att;
    float4 w0 = wav[hl], w1 = wav[hl + 16], w2 = wav[hl + 32], w3 = wav[hl + 48];

    Run st;
    st.a0 = st.a1 = st.a2 = st.a3 = make_float4(0.f, 0.f, 0.f, 0.f);
    st.rmax = -INFINITY; st.rcnt = 0; st.cur = -1; st.qcur = 0.f;

    const float4 z4 = make_float4(0.f, 0.f, 0.f, 0.f);

    for (int e0 = lo + 2 * w; e0 < hi; e0 += 32) {
        int eA = e0 + half;
        int eB = e0 + 16 + half;
        bool vA = eA < hi, vB = eB < hi;
        int gA = st.cur, gB = st.cur;
        int sA = 1, sB = 1;
        float4 xa0 = z4, xa1 = z4, xa2 = z4, xa3 = z4;
        float4 xb0 = z4, xb1 = z4, xb2 = z4, xb3 = z4;
        if (vA) {
            gA = __ldg(batch + eA);
            sA = __ldg(sel + eA);
            const float4* r = (const float4*)(x + (size_t)eA * H);
            xa0 = __ldg(r + hl); xa1 = __ldg(r + hl + 16);
            xa2 = __ldg(r + hl + 32); xa3 = __ldg(r + hl + 48);
        }
        if (vB) {
            gB = __ldg(batch + eB);
            sB = __ldg(sel + eB);
            const float4* r = (const float4*)(x + (size_t)eB * H);
            xb0 = __ldg(r + hl); xb1 = __ldg(r + hl + 16);
            xb2 = __ldg(r + hl + 32); xb3 = __ldg(r + hl + 48);
        }
        proc(st, vA, gA, sA, xa0, xa1, xa2, xa3, w0, w1, w2, w3, eA, hl);
        proc(st, vB, gB, sB, xb0, xb1, xb2, xb3, w0, w1, w2, w3, eB, hl);
    }
    flush_run(st, hl);
}

// ---------------- fused post: softmax+logits (blocks [0,G)) + stop head ----
__device__ __forceinline__ int lower_bound_batch(const int* batch, int E, int key) {
    int lo = 0, hi = E;
    while (lo < hi) {
        int mid = (lo + hi) >> 1;
        if (__ldg(batch + mid) < key) lo = mid + 1; else hi = mid;
    }
    return lo;
}

__device__ __forceinline__ float block_sum(float v, float* red) {
    int l = threadIdx.x & 31, w = threadIdx.x >> 5;
    #pragma unroll
    for (int sh = 16; sh; sh >>= 1) v += __shfl_xor_sync(0xFFFFFFFFu, v, sh);
    if (l == 0) red[w] = v;
    __syncthreads();
    if (w == 0) {
        float x = (l < 8) ? red[l] : 0.f;
        #pragma unroll
        for (int sh = 4; sh; sh >>= 1) x += __shfl_xor_sync(0xFFFFFFFFu, x, sh);
        if (l == 0) red[0] = x;
    }
    __syncthreads();
    float r = red[0];
    __syncthreads();
    return r;
}

__global__ void __launch_bounds__(256) post_k(
        const int* __restrict__ batch, const int* __restrict__ sel,
        const float* __restrict__ qtok, const float* __restrict__ W_edge,
        const float* __restrict__ ln_g, const float* __restrict__ ln_b,
        const float* __restrict__ W1, const float* __restrict__ b1,
        const float* __restrict__ W2, const float* __restrict__ b2,
        float* __restrict__ out_edge, float* __restrict__ out_stop,
        float* __restrict__ out_pooled, int E, int G) {
    int t = threadIdx.x;
    int l = t & 31, w = t >> 5;

    if (blockIdx.x < (unsigned)G) {
        // -------- segment softmax + edge logits --------
        __shared__ float red[32];
        __shared__ float s_inv;
        int g = blockIdx.x;
        int lo = lower_bound_batch(batch, E, g);
        int hi = lower_bound_batch(batch, E, g + 1);
        if (lo >= hi) return;

        float m = o2f(g_maxenc[g]);
        float s = 0.f;
        for (int e = lo + t; e < hi; e += 256)
            if (__ldg(sel + e) == 0) s += __expf(__ldg(g_att + e) - m);
        #pragma unroll
        for (int sh = 16; sh; sh >>= 1) s += __shfl_xor_sync(0xFFFFFFFFu, s, sh);
        if (l == 0) red[w] = s;
        __syncthreads();
        if (w == 0) {
            float v = (l < 8) ? red[l] : 0.f;
            #pragma unroll
            for (int sh = 4; sh; sh >>= 1) v += __shfl_xor_sync(0xFFFFFFFFu, v, sh);
            if (l == 0) s_inv = 1.0f / fmaxf(v, F32_EPS);
        }
        __syncthreads();
        float inv = s_inv;
        for (int e = lo + t; e < hi; e += 256) {
            float p = 0.f;
            if (__ldg(sel + e) == 0) p = __expf(__ldg(g_att + e) - m) * inv;
            out_edge[e] = logf(fmaxf(p, F32_EPS));
        }
    } else {
        // -------- pooled + LayerNorm + MLP + stop logit --------
        __shared__ float xsh[2 * H];
        __shared__ float ssh[H];
        __shared__ float red[32];
        int g = blockIdx.x - G;

        ssh[t] = g_S[g * H + t];
        __syncthreads();

        float denom = fmaxf((float)g_cnt[g], 1.0f);
        float acc = 0.f;
        const float4* wr = (const float4*)(W_edge + (size_t)t * H);
        #pragma unroll 8
        for (int j = 0; j < H / 4; j++) {
            float4 w4 = wr[j];
            acc += w4.x * ssh[4 * j] + w4.y * ssh[4 * j + 1]
                 + w4.z * ssh[4 * j + 2] + w4.w * ssh[4 * j + 3];
        }
        float pe = acc / denom;
        out_pooled[(size_t)g * H + t] = pe;
        float qv = qtok[(size_t)g * H + t];

        float mu = block_sum(pe + qv, red) * (1.0f / (2 * H));
        float d0 = pe - mu, d1 = qv - mu;
        float var = block_sum(d0 * d0 + d1 * d1, red) * (1.0f / (2 * H));
        float rstd = rsqrtf(var + LN_EPS);
        xsh[t]     = d0 * rstd * ln_g[t]     + ln_b[t];
        xsh[H + t] = d1 * rstd * ln_g[H + t] + ln_b[H + t];
        __syncthreads();

        float a1 = b1[t];
        const float4* w1r = (const float4*)(W1 + (size_t)t * (2 * H));
        #pragma unroll 8
        for (int j = 0; j < (2 * H) / 4; j++) {
            float4 w4 = w1r[j];
            a1 += w4.x * xsh[4 * j] + w4.y * xsh[4 * j + 1]
                + w4.z * xsh[4 * j + 2] + w4.w * xsh[4 * j + 3];
        }
        float h1 = 0.5f * a1 * (1.0f + erff(a1 * 0.70710678118654752f));

        float tot = block_sum(h1 * W2[t], red);
        if (t == 0) out_stop[g] = tot + b2[0];
    }
}

// ---------------- launch ----------------
extern "C" void kernel_launch(void* const* d_in, const int* in_sizes, int n_in,
                              void* d_out, int out_size) {
    const float* edge_tokens = (const float*)d_in[0];
    const float* qtok        = (const float*)d_in[1];
    const int*   batch       = (const int*)d_in[2];
    const int*   sel         = (const int*)d_in[3];
    const float* W_edge      = (const float*)d_in[4];
    const float* W_query     = (const float*)d_in[5];
    const float* att_vec     = (const float*)d_in[6];
    const float* ln_g        = (const float*)d_in[7];
    const float* ln_b        = (const float*)d_in[8];
    const float* W1          = (const float*)d_in[9];
    const float* b1          = (const float*)d_in[10];
    const float* W2          = (const float*)d_in[11];
    const float* b2          = (const float*)d_in[12];

    int E = in_sizes[0] / H;
    int G = in_sizes[1] / H;

    float* out = (float*)d_out;
    float* out_edge   = out;            // [E]
    float* out_stop   = out + E;        // [G]
    float* out_pooled = out + E + G;    // [G*H]

    setup_k<<<49, 256>>>(W_edge, W_query, att_vec, qtok, G);
    pass1_k<<<NBLK_P1, 256>>>(edge_tokens, batch, sel, E);
    post_k<<<2 * G, 256>>>(batch, sel, qtok, W_edge, ln_g, ln_b, W1, b1, W2, b2,
                           out_edge, out_stop, out_pooled, E, G);
}

// round 6
// speedup vs baseline: 1.4540x; 1.4540x over previous
#include <cuda_runtime.h>
#include <math.h>

#define H 256
#define MAXE 500000
#define MAXG 256
#define FRONTIER_BONUS 0.5f
#define LN_EPS 1e-5f
#define F32_EPS 1.1920929e-07f
#define NBLK_P1 1184
#define STOPG 4

// ---------------- device scratch (single memset-able struct) ----------------
// __align__(16) is REQUIRED: pass1_k does float4 (LDG.128) loads from w_att
// and float4-indexed atomics into S. A plain struct of floats is only
// 4-aligned and traps with "misaligned address".
struct __align__(16) Scratch {
    float    S[MAXG * H];     // segment sums of edge_tokens
    float    w_att[H];        // att_vec @ W_edge  (atomic partials)
    float    w_q[H];          // att_vec @ W_query (atomic partials)
    unsigned maxenc[MAXG];    // order-preserving-uint segment max (0 == -inf)
    int      cnt[MAXG];       // edges per graph
};
__device__ Scratch g_z;
__device__ float g_qatt[MAXG];   // fully overwritten each run
__device__ float g_att[MAXE];    // fully overwritten each run

// order-preserving float <-> uint; memset-0 acts as -infinity identity
__device__ __forceinline__ unsigned fenc(float f) {
    unsigned u = (unsigned)__float_as_int(f);
    return (u & 0x80000000u) ? ~u : (u | 0x80000000u);
}
__device__ __forceinline__ float fdec(unsigned u) {
    unsigned v = (u & 0x80000000u) ? (u & 0x7FFFFFFFu) : ~u;
    return __int_as_float((int)v);
}

// ---------------- w_att / w_q partials (32 blocks, 16 rows each) ----------
__global__ void __launch_bounds__(256) prew_k(const float* __restrict__ W_edge,
                       const float* __restrict__ W_query,
                       const float* __restrict__ att_vec) {
    int j = threadIdx.x;
    int m = blockIdx.x >> 4;              // 0: W_edge, 1: W_query
    int c = blockIdx.x & 15;              // row chunk of 16
    const float* W = m ? W_query : W_edge;
    int i0 = c * 16;
    float s = 0.f;
    #pragma unroll
    for (int i = 0; i < 16; i++)
        s = fmaf(__ldg(att_vec + i0 + i), __ldg(W + (i0 + i) * H + j), s);
    atomicAdd((m ? g_z.w_q : g_z.w_att) + j, s);
}

// ---------------- qatt[g] = question_tokens[g] . w_q ----------------
__global__ void __launch_bounds__(256) qatt_k(const float* __restrict__ qtok, int G) {
    int w = threadIdx.x >> 5, l = threadIdx.x & 31;
    int g = blockIdx.x * 8 + w;
    if (g >= G) return;
    float s = 0.f;
    #pragma unroll
    for (int k = 0; k < 8; k++) {
        int j = l + 32 * k;
        s = fmaf(qtok[(size_t)g * H + j], g_z.w_q[j], s);
    }
    #pragma unroll
    for (int sh = 16; sh; sh >>= 1) s += __shfl_xor_sync(0xFFFFFFFFu, s, sh);
    if (l == 0) g_qatt[g] = s;
}

// ---------------- main streaming pass: warp-per-edge, x4 unroll ----------
struct RunState {
    float4 a0, a1;
    float rmax, qcur;
    int cur, rcnt;
};

__device__ __forceinline__ void flush_run(RunState& st, int l) {
    if (st.cur < 0) return;
    float* Sp = &g_z.S[st.cur * H];
    atomicAdd(Sp + 4 * l + 0, st.a0.x);
    atomicAdd(Sp + 4 * l + 1, st.a0.y);
    atomicAdd(Sp + 4 * l + 2, st.a0.z);
    atomicAdd(Sp + 4 * l + 3, st.a0.w);
    atomicAdd(Sp + 128 + 4 * l + 0, st.a1.x);
    atomicAdd(Sp + 128 + 4 * l + 1, st.a1.y);
    atomicAdd(Sp + 128 + 4 * l + 2, st.a1.z);
    atomicAdd(Sp + 128 + 4 * l + 3, st.a1.w);
    if (l == 0) {
        atomicMax(&g_z.maxenc[st.cur], fenc(st.rmax));
        atomicAdd(&g_z.cnt[st.cur], st.rcnt);
    }
}

__device__ __forceinline__ void process_edge(RunState& st, int g, int selv,
                                             float4 x0, float4 x1,
                                             float4 wa0, float4 wa1,
                                             int e, int l) {
    if (g != st.cur) {
        flush_run(st, l);
        st.a0 = make_float4(0.f, 0.f, 0.f, 0.f);
        st.a1 = make_float4(0.f, 0.f, 0.f, 0.f);
        st.rmax = -INFINITY; st.rcnt = 0; st.cur = g;
        st.qcur = g_qatt[g];
    }
    st.a0.x += x0.x; st.a0.y += x0.y; st.a0.z += x0.z; st.a0.w += x0.w;
    st.a1.x += x1.x; st.a1.y += x1.y; st.a1.z += x1.z; st.a1.w += x1.w;
    float d = x0.x * wa0.x + x0.y * wa0.y + x0.z * wa0.z + x0.w * wa0.w
            + x1.x * wa1.x + x1.y * wa1.y + x1.z * wa1.z + x1.w * wa1.w;
    #pragma unroll
    for (int sh = 16; sh; sh >>= 1) d += __shfl_xor_sync(0xFFFFFFFFu, d, sh);
    float r = d + st.qcur;
    r = r > 0.f ? r : 0.2f * r;                       // LeakyReLU(0.2)
    if (selv == 0) r += FRONTIER_BONUS;               // candidate == frontier
    if (l == 0) g_att[e] = r;
    st.rmax = fmaxf(st.rmax, r);
    st.rcnt++;
}

__global__ void __launch_bounds__(256) pass1_k(const float* __restrict__ x,
                        const int* __restrict__ batch,
                        const int* __restrict__ sel,
                        int E) {
    int chunk = (E + NBLK_P1 - 1) / NBLK_P1;
    int lo = blockIdx.x * chunk;
    int hi = min(E, lo + chunk);
    int w = threadIdx.x >> 5, l = threadIdx.x & 31;

    const float4* wav = (const float4*)g_z.w_att;
    float4 wa0 = wav[l];
    float4 wa1 = wav[32 + l];

    RunState st;
    st.a0 = make_float4(0.f, 0.f, 0.f, 0.f);
    st.a1 = make_float4(0.f, 0.f, 0.f, 0.f);
    st.cur = -1; st.rcnt = 0; st.rmax = -INFINITY; st.qcur = 0.f;

    int e = lo + w;
    // x4 unroll: all loads unconditional and front-batched (8 LDG.128 in flight)
    for (; e + 24 < hi; e += 32) {
        int e1 = e + 8, e2 = e + 16, e3 = e + 24;
        int g0 = __ldg(batch + e);
        int g1 = __ldg(batch + e1);
        int g2 = __ldg(batch + e2);
        int g3 = __ldg(batch + e3);
        int s0 = __ldg(sel + e);
        int s1 = __ldg(sel + e1);
        int s2 = __ldg(sel + e2);
        int s3 = __ldg(sel + e3);
        const float4* r0 = (const float4*)(x + (size_t)e  * H);
        const float4* r1 = (const float4*)(x + (size_t)e1 * H);
        const float4* r2 = (const float4*)(x + (size_t)e2 * H);
        const float4* r3 = (const float4*)(x + (size_t)e3 * H);
        float4 xa0 = __ldg(r0 + l), xa1 = __ldg(r0 + 32 + l);
        float4 xb0 = __ldg(r1 + l), xb1 = __ldg(r1 + 32 + l);
        float4 xc0 = __ldg(r2 + l), xc1 = __ldg(r2 + 32 + l);
        float4 xd0 = __ldg(r3 + l), xd1 = __ldg(r3 + 32 + l);
        process_edge(st, g0, s0, xa0, xa1, wa0, wa1, e,  l);
        process_edge(st, g1, s1, xb0, xb1, wa0, wa1, e1, l);
        process_edge(st, g2, s2, xc0, xc1, wa0, wa1, e2, l);
        process_edge(st, g3, s3, xd0, xd1, wa0, wa1, e3, l);
    }
    for (; e < hi; e += 8) {
        int g = __ldg(batch + e);
        int s = __ldg(sel + e);
        const float4* row = (const float4*)(x + (size_t)e * H);
        float4 x0 = __ldg(row + l);
        float4 x1 = __ldg(row + 32 + l);
        process_edge(st, g, s, x0, x1, wa0, wa1, e, l);
    }
    flush_run(st, l);
}

// ---------------- fused post: softmax (blocks [0,G)) + stop head (4 g/block)
__device__ __forceinline__ int lower_bound_batch(const int* batch, int E, int key) {
    int lo = 0, hi = E;
    while (lo < hi) {
        int mid = (lo + hi) >> 1;
        if (__ldg(batch + mid) < key) lo = mid + 1; else hi = mid;
    }
    return lo;
}

__device__ __forceinline__ void block_sum4(float v[STOPG], float4* red4, float out[STOPG]) {
    int l = threadIdx.x & 31, w = threadIdx.x >> 5;
    #pragma unroll
    for (int sh = 16; sh; sh >>= 1) {
        #pragma unroll
        for (int gg = 0; gg < STOPG; gg++)
            v[gg] += __shfl_xor_sync(0xFFFFFFFFu, v[gg], sh);
    }
    if (l == 0) red4[w] = make_float4(v[0], v[1], v[2], v[3]);
    __syncthreads();
    if (w == 0) {
        float4 xv = (l < 8) ? red4[l] : make_float4(0.f, 0.f, 0.f, 0.f);
        #pragma unroll
        for (int sh = 4; sh; sh >>= 1) {
            xv.x += __shfl_xor_sync(0xFFFFFFFFu, xv.x, sh);
            xv.y += __shfl_xor_sync(0xFFFFFFFFu, xv.y, sh);
            xv.z += __shfl_xor_sync(0xFFFFFFFFu, xv.z, sh);
            xv.w += __shfl_xor_sync(0xFFFFFFFFu, xv.w, sh);
        }
        if (l == 0) red4[0] = xv;
    }
    __syncthreads();
    float4 r = red4[0];
    out[0] = r.x; out[1] = r.y; out[2] = r.z; out[3] = r.w;
    __syncthreads();
}

__global__ void __launch_bounds__(256) post_k(
        const int* __restrict__ batch, const int* __restrict__ sel,
        const float* __restrict__ qtok, const float* __restrict__ W_edge,
        const float* __restrict__ ln_g, const float* __restrict__ ln_b,
        const float* __restrict__ W1, const float* __restrict__ b1,
        const float* __restrict__ W2, const float* __restrict__ b2,
        float* __restrict__ out_edge, float* __restrict__ out_stop,
        float* __restrict__ out_pooled, int E, int G) {
    int t = threadIdx.x;
    int l = t & 31, w = t >> 5;

    if (blockIdx.x < (unsigned)G) {
        // -------- segment softmax + edge logits --------
        __shared__ float red[32];
        __shared__ float s_inv;
        int g = blockIdx.x;
        int lo = lower_bound_batch(batch, E, g);
        int hi = lower_bound_batch(batch, E, g + 1);
        if (lo >= hi) return;

        float m = fdec(g_z.maxenc[g]);
        float s = 0.f;
        for (int e = lo + t; e < hi; e += 256)
            if (__ldg(sel + e) == 0) s += __expf(__ldg(g_att + e) - m);
        #pragma unroll
        for (int sh = 16; sh; sh >>= 1) s += __shfl_xor_sync(0xFFFFFFFFu, s, sh);
        if (l == 0) red[w] = s;
        __syncthreads();
        if (w == 0) {
            float v = (l < 8) ? red[l] : 0.f;
            #pragma unroll
            for (int sh = 4; sh; sh >>= 1) v += __shfl_xor_sync(0xFFFFFFFFu, v, sh);
            if (l == 0) s_inv = 1.0f / fmaxf(v, F32_EPS);
        }
        __syncthreads();
        float inv = s_inv;
        for (int e = lo + t; e < hi; e += 256) {
            float p = 0.f;
            if (__ldg(sel + e) == 0) p = __expf(__ldg(g_att + e) - m) * inv;
            out_edge[e] = logf(fmaxf(p, F32_EPS));
        }
    } else {
        // -------- stop head: STOPG graphs per block --------
        __shared__ __align__(16) float ssh[STOPG][H];       // S rows
        __shared__ __align__(16) float xsh[STOPG][2 * H];   // layernormed inputs
        __shared__ float4 red4[32];
        int g0 = (blockIdx.x - G) * STOPG;

        #pragma unroll
        for (int gg = 0; gg < STOPG; gg++) {
            int g = g0 + gg;
            ssh[gg][t] = (g < G) ? g_z.S[g * H + t] : 0.f;
        }
        __syncthreads();

        // pooled[g][t] = (S[g] . W_edge[t,:]) / denom — W_edge row read once, used x4
        float acc[STOPG];
        #pragma unroll
        for (int gg = 0; gg < STOPG; gg++) acc[gg] = 0.f;
        const float4* wr = (const float4*)(W_edge + (size_t)t * H);
        #pragma unroll 4
        for (int j = 0; j < H / 4; j++) {
            float4 w4 = __ldg(wr + j);
            #pragma unroll
            for (int gg = 0; gg < STOPG; gg++) {
                float4 s4 = ((const float4*)ssh[gg])[j];
                acc[gg] = fmaf(w4.x, s4.x, fmaf(w4.y, s4.y,
                          fmaf(w4.z, s4.z, fmaf(w4.w, s4.w, acc[gg]))));
            }
        }
        float pe[STOPG], qv[STOPG];
        #pragma unroll
        for (int gg = 0; gg < STOPG; gg++) {
            int g = g0 + gg;
            float denom = (g < G) ? fmaxf((float)g_z.cnt[g], 1.0f) : 1.0f;
            pe[gg] = acc[gg] / denom;
            qv[gg] = (g < G) ? qtok[(size_t)g * H + t] : 0.f;
            if (g < G) out_pooled[(size_t)g * H + t] = pe[gg];
        }

        // LayerNorm over 512 per graph
        float v[STOPG], mu[STOPG], var[STOPG];
        #pragma unroll
        for (int gg = 0; gg < STOPG; gg++) v[gg] = pe[gg] + qv[gg];
        block_sum4(v, red4, mu);
        float d0[STOPG], d1[STOPG];
        #pragma unroll
        for (int gg = 0; gg < STOPG; gg++) {
            mu[gg] *= (1.0f / (2 * H));
            d0[gg] = pe[gg] - mu[gg];
            d1[gg] = qv[gg] - mu[gg];
            v[gg] = d0[gg] * d0[gg] + d1[gg] * d1[gg];
        }
        block_sum4(v, red4, var);
        float lg0 = ln_g[t], lb0 = ln_b[t], lg1 = ln_g[H + t], lb1 = ln_b[H + t];
        #pragma unroll
        for (int gg = 0; gg < STOPG; gg++) {
            float rstd = rsqrtf(var[gg] * (1.0f / (2 * H)) + LN_EPS);
            xsh[gg][t]     = d0[gg] * rstd * lg0 + lb0;
            xsh[gg][H + t] = d1[gg] * rstd * lg1 + lb1;
        }
        __syncthreads();

        // h1[t] = gelu(xn . W1[t,:] + b1[t]) — W1 row read once, used x4
        float a1[STOPG];
        float bb = b1[t];
        #pragma unroll
        for (int gg = 0; gg < STOPG; gg++) a1[gg] = bb;
        const float4* w1r = (const float4*)(W1 + (size_t)t * (2 * H));
        #pragma unroll 4
        for (int j = 0; j < (2 * H) / 4; j++) {
            float4 w4 = __ldg(w1r + j);
            #pragma unroll
            for (int gg = 0; gg < STOPG; gg++) {
                float4 x4 = ((const float4*)xsh[gg])[j];
                a1[gg] = fmaf(w4.x, x4.x, fmaf(w4.y, x4.y,
                         fmaf(w4.z, x4.z, fmaf(w4.w, x4.w, a1[gg]))));
            }
        }
        float w2v = W2[t];
        #pragma unroll
        for (int gg = 0; gg < STOPG; gg++) {
            float h1 = 0.5f * a1[gg] * (1.0f + erff(a1[gg] * 0.70710678118654752f));
            v[gg] = h1 * w2v;
        }
        float tot[STOPG];
        block_sum4(v, red4, tot);
        if (t == 0) {
            float bias = b2[0];
            #pragma unroll
            for (int gg = 0; gg < STOPG; gg++)
                if (g0 + gg < G) out_stop[g0 + gg] = tot[gg] + bias;
        }
    }
}

// ---------------- launch ----------------
extern "C" void kernel_launch(void* const* d_in, const int* in_sizes, int n_in,
                              void* d_out, int out_size) {
    const float* edge_tokens = (const float*)d_in[0];
    const float* qtok        = (const float*)d_in[1];
    const int*   batch       = (const int*)d_in[2];
    const int*   sel         = (const int*)d_in[3];
    const float* W_edge      = (const float*)d_in[4];
    const float* W_query     = (const float*)d_in[5];
    const float* att_vec     = (const float*)d_in[6];
    const float* ln_g        = (const float*)d_in[7];
    const float* ln_b        = (const float*)d_in[8];
    const float* W1          = (const float*)d_in[9];
    const float* b1          = (const float*)d_in[10];
    const float* W2          = (const float*)d_in[11];
    const float* b2          = (const float*)d_in[12];

    int E = in_sizes[0] / H;
    int G = in_sizes[1] / H;

    float* out = (float*)d_out;
    float* out_edge   = out;            // [E]
    float* out_stop   = out + E;        // [G]
    float* out_pooled = out + E + G;    // [G*H]

    void* zp = nullptr;
    cudaGetSymbolAddress(&zp, g_z);
    cudaMemsetAsync(zp, 0, sizeof(Scratch));

    prew_k<<<32, 256>>>(W_edge, W_query, att_vec);
    qatt_k<<<(G + 7) / 8, 256>>>(qtok, G);
    pass1_k<<<NBLK_P1, 256>>>(edge_tokens, batch, sel, E);
    post_k<<<G + (G + STOPG - 1) / STOPG, 256>>>(
        batch, sel, qtok, W_edge, ln_g, ln_b, W1, b1, W2, b2,
        out_edge, out_stop, out_pooled, E, G);
}